// round 7
// baseline (speedup 1.0000x reference)
#include <cuda_runtime.h>
#include <cuda_bf16.h>
#include <cstdint>

#define HB 128      // batch
#define HC 64       // states
#define NEG_INF (-3.402823466e38f)
// float32(0.5 * log(2*pi))
#define HALF_LOG2PI 0.91893853320467274178f

__device__ __forceinline__ float warp_max_bfly(float v) {
    #pragma unroll
    for (int off = 16; off >= 1; off >>= 1)
        v = fmaxf(v, __shfl_xor_sync(0xffffffff, v, off));
    return v;
}

// Emission log-prob matching the reference's float32 op sequence exactly:
//   z_d = (x_d - mu_d) / sigma_d                      (sub, div.rn)
//   e_d = ((-0.5*z_d)*z_d - log(sigma_d)) - 0.5*log2pi (mul, mul, sub, sub)
//   lp  = ((e0 + e1) + e2) + e3                        (sequential adds)
// No fma contraction anywhere.
__device__ __forceinline__ float emis_ref(float4 xv, const float* mu,
                                          const float* sg, const float* lsg) {
    float z0 = __fdiv_rn(__fsub_rn(xv.x, mu[0]), sg[0]);
    float z1 = __fdiv_rn(__fsub_rn(xv.y, mu[1]), sg[1]);
    float z2 = __fdiv_rn(__fsub_rn(xv.z, mu[2]), sg[2]);
    float z3 = __fdiv_rn(__fsub_rn(xv.w, mu[3]), sg[3]);
    float e0 = __fsub_rn(__fsub_rn(__fmul_rn(__fmul_rn(-0.5f, z0), z0), lsg[0]), HALF_LOG2PI);
    float e1 = __fsub_rn(__fsub_rn(__fmul_rn(__fmul_rn(-0.5f, z1), z1), lsg[1]), HALF_LOG2PI);
    float e2 = __fsub_rn(__fsub_rn(__fmul_rn(__fmul_rn(-0.5f, z2), z2), lsg[2]), HALF_LOG2PI);
    float e3 = __fsub_rn(__fsub_rn(__fmul_rn(__fmul_rn(-0.5f, z3), z3), lsg[3]), HALF_LOG2PI);
    return __fadd_rn(__fadd_rn(__fadd_rn(e0, e1), e2), e3);
}

__global__ __launch_bounds__(128, 1)
void MyHMM_14353780703777_kernel(const float* __restrict__ x,
                                 const float* __restrict__ means,
                                 const float* __restrict__ stds,
                                 const float* __restrict__ logA,
                                 const float* __restrict__ logpi,
                                 float* __restrict__ out, int T) {
    extern __shared__ char smem[];
    float4* xs          = (float4*)smem;                       // T * 16 bytes
    float*  abuf        = (float*)(smem + 16 * (size_t)T);     // 2*64 (forward alpha dbl-buf)
    float*  dbuf        = abuf + 128;                          // 2*64 (viterbi d dbl-buf)
    float*  Abuf        = dbuf + 128;                          // 64*65 padded raw logA
    float*  rowmx       = Abuf + 64 * 65;                      // 64 row maxes
    float*  rowls       = rowmx + 64;                          // 64 row lse's
    float*  piaux       = rowls + 64;                          // [0]=pimax, [1]=pilse (pad to 16)
    unsigned char* psi  = (unsigned char*)(piaux + 16);        // (T-1)*64 backpointers

    const int b = blockIdx.x;
    const int tid = threadIdx.x;
    const float* xb = x + (size_t)b * T * 6;

    // ---- preload x[b, :, 0:4] as float4 ----
    for (int i = tid; i < T; i += 128) {
        const float* p = xb + i * 6;
        xs[i] = make_float4(p[0], p[1], p[2], p[3]);
    }
    // ---- load raw log_A into padded smem ----
    for (int i = tid; i < HC * HC; i += 128) {
        Abuf[(i >> 6) * 65 + (i & 63)] = logA[i];
    }
    __syncthreads();

    // ---- log_softmax prep for A rows (accurate expf/logf, sequential sum,
    //      matching jax.nn.log_softmax's (x - max) - log(sum(exp(x - max)))) ----
    if (tid < HC) {
        const int r = tid;
        float mx = NEG_INF;
        #pragma unroll 8
        for (int j = 0; j < HC; j++) mx = fmaxf(mx, Abuf[r * 65 + j]);
        float s = 0.0f;
        #pragma unroll 8
        for (int j = 0; j < HC; j++)
            s = __fadd_rn(s, expf(__fsub_rn(Abuf[r * 65 + j], mx)));
        rowmx[r] = mx;
        rowls[r] = logf(s);
    }
    if (tid == 0) {
        float mx = NEG_INF;
        for (int j = 0; j < HC; j++) mx = fmaxf(mx, logpi[j]);
        float s = 0.0f;
        for (int j = 0; j < HC; j++)
            s = __fadd_rn(s, expf(__fsub_rn(logpi[j], mx)));
        piaux[0] = mx;
        piaux[1] = logf(s);
    }
    __syncthreads();
    const float pimx = piaux[0];
    const float pils = piaux[1];

    if (tid < 32) {
        // ========== FORWARD (1 warp, 2 states/thread, prob-space, deferred renorm) ==========
        const int c0 = tid, c1 = tid + 32;
        float mu0[4], sg0[4], lsg0[4], mu1[4], sg1[4], lsg1[4];
        #pragma unroll
        for (int d = 0; d < 4; d++) {
            sg0[d] = __fadd_rn(fmaxf(stds[c0 * 6 + d], 0.0f), 0.1f);
            sg1[d] = __fadd_rn(fmaxf(stds[c1 * 6 + d], 0.0f), 0.1f);
            mu0[d] = means[c0 * 6 + d]; mu1[d] = means[c1 * 6 + d];
            lsg0[d] = logf(sg0[d]);
            lsg1[d] = logf(sg1[d]);
        }
        const float pil0 = __fsub_rn(__fsub_rn(logpi[c0], pimx), pils);
        const float pil1 = __fsub_rn(__fsub_rn(logpi[c1], pimx), pils);

        // register-resident transition columns (prob space; fast exp is fine here)
        float Ae0[64], Ae1[64];
        #pragma unroll
        for (int j = 0; j < 64; j++) {
            float sh0 = __fsub_rn(__fsub_rn(Abuf[j * 65 + c0], rowmx[j]), rowls[j]);
            float sh1 = __fsub_rn(__fsub_rn(Abuf[j * 65 + c1], rowmx[j]), rowls[j]);
            Ae0[j] = __expf(sh0);
            Ae1[j] = __expf(sh1);
        }

        // t = 0
        float4 xv = xs[0];
        float lpA = __fadd_rn(emis_ref(xv, mu0, sg0, lsg0), pil0);
        float lpB = __fadd_rn(emis_ref(xv, mu1, sg1, lsg1), pil1);
        float g = warp_max_bfly(fmaxf(lpA, lpB));
        float u0 = __expf(lpA - g);
        float u1 = __expf(lpB - g);
        double acc = (double)g;

        float* aprev = abuf;
        float* acur  = abuf + 64;
        aprev[c0] = u0; aprev[c1] = u1;
        __syncwarp();

        float rprev = 1.0f;           // 1/m_{t-1}
        float lpend = 0.0f;           // log(m_{t-1}) pending
        float w0 = u0, w1 = u1;

        for (int t = 1; t < T; t++) {
            float4 xq = xs[t];
            float l0 = emis_ref(xq, mu0, sg0, lsg0);
            float l1 = emis_ref(xq, mu1, sg1, lsg1);
            // reduction overlaps the matvec (MIO vs FMA pipes)
            float gt = warp_max_bfly(fmaxf(l0, l1));

            float v0a = 0.0f, v0b = 0.0f, v1a = 0.0f, v1b = 0.0f;
            #pragma unroll
            for (int j = 0; j < 64; j += 4) {
                float4 a = *(const float4*)(aprev + j);
                v0a = fmaf(a.x, Ae0[j],     v0a);
                v1a = fmaf(a.x, Ae1[j],     v1a);
                v0b = fmaf(a.y, Ae0[j + 1], v0b);
                v1b = fmaf(a.y, Ae1[j + 1], v1b);
                v0a = fmaf(a.z, Ae0[j + 2], v0a);
                v1a = fmaf(a.z, Ae1[j + 2], v1a);
                v0b = fmaf(a.w, Ae0[j + 3], v0b);
                v1b = fmaf(a.w, Ae1[j + 3], v1b);
            }
            float e0 = __expf(l0 - gt) * rprev;
            float e1 = __expf(l1 - gt) * rprev;
            w0 = e0 * (v0a + v0b);
            w1 = e1 * (v1a + v1b);
            acur[c0] = w0; acur[c1] = w1;       // store BEFORE reduction
            __syncwarp();
            acc += (double)gt + (double)lpend;

            float m = warp_max_bfly(fmaxf(w0, w1));
            rprev = __frcp_rn(m);
            lpend = __logf(m);

            float* tmp = aprev; aprev = acur; acur = tmp;
        }

        // logp_x = acc + log(m_{T-1}) + log(sum of last stored w)
        float s = w0 + w1;
        #pragma unroll
        for (int off = 16; off >= 1; off >>= 1)
            s += __shfl_xor_sync(0xffffffff, s, off);
        if (tid == 0) out[b] = (float)(acc + (double)lpend + (double)__logf(s));

    } else if (tid >= 64) {
        // ========== VITERBI (2 warps, 1 state/thread, ref-exact float32 ops) ==========
        const int c = tid - 64;
        float mu[4], sg[4], lsg[4];
        #pragma unroll
        for (int d = 0; d < 4; d++) {
            sg[d]  = __fadd_rn(fmaxf(stds[c * 6 + d], 0.0f), 0.1f);
            mu[d]  = means[c * 6 + d];
            lsg[d] = logf(sg[d]);
        }
        const float pil = __fsub_rn(__fsub_rn(logpi[c], pimx), pils);

        // normalized logA column: (A - rowmax) - rowlse, exactly as log_softmax
        float Al[64];
        #pragma unroll
        for (int j = 0; j < 64; j++)
            Al[j] = __fsub_rn(__fsub_rn(Abuf[j * 65 + c], rowmx[j]), rowls[j]);

        float* dprev = dbuf;
        float* dcur  = dbuf + 64;

        float4 xv = xs[0];
        dprev[c] = __fadd_rn(emis_ref(xv, mu, sg, lsg), pil);
        asm volatile("bar.sync 1, 64;" ::: "memory");

        for (int t = 1; t < T; t++) {
            float4 xq = xs[t];
            float lp = emis_ref(xq, mu, sg, lsg);
            float best = NEG_INF;
            int bi = 0;
            // first-max semantics (strict >, ascending j) == jnp.argmax
            #pragma unroll
            for (int j = 0; j < 64; j += 4) {
                float4 dv = *(const float4*)(dprev + j);
                float v;
                v = __fadd_rn(dv.x, Al[j]);     if (v > best) { best = v; bi = j; }
                v = __fadd_rn(dv.y, Al[j + 1]); if (v > best) { best = v; bi = j + 1; }
                v = __fadd_rn(dv.z, Al[j + 2]); if (v > best) { best = v; bi = j + 2; }
                v = __fadd_rn(dv.w, Al[j + 3]); if (v > best) { best = v; bi = j + 3; }
            }
            dcur[c] = __fadd_rn(best, lp);
            psi[(t - 1) * 64 + c] = (unsigned char)bi;
            asm volatile("bar.sync 1, 64;" ::: "memory");
            float* tmp = dprev; dprev = dcur; dcur = tmp;
        }

        // backtrack (single thread; psi in smem -> LDS-latency chase)
        if (c == 0) {
            float bb = dprev[0]; int cl = 0;
            #pragma unroll 8
            for (int j = 1; j < 64; j++) {
                float v = dprev[j];
                if (v > bb) { bb = v; cl = j; }
            }
            float* oc = out + HB + (size_t)b * T;
            int cc = cl;
            oc[T - 1] = (float)cc;
            for (int t = T - 2; t >= 0; --t) {
                cc = psi[t * 64 + cc];
                oc[t] = (float)cc;
            }
        }
    }
    // tid 32..63: idle warp (never touches named barrier 1)
}

extern "C" void kernel_launch(void* const* d_in, const int* in_sizes, int n_in,
                              void* d_out, int out_size) {
    const float* x      = (const float*)d_in[0];
    const float* means  = (const float*)d_in[1];
    const float* stds   = (const float*)d_in[2];
    const float* logA   = (const float*)d_in[3];
    const float* logpi  = (const float*)d_in[4];
    float* out = (float*)d_out;

    int T = in_sizes[0] / (HB * 6);   // 2050

    size_t smem = 16 * (size_t)T          // xs
                + 128 * sizeof(float)     // abuf
                + 128 * sizeof(float)     // dbuf
                + 64 * 65 * sizeof(float) // Abuf (padded)
                + (64 + 64 + 16) * sizeof(float) // rowmx, rowls, piaux
                + (size_t)(T - 1) * 64;   // psi

    cudaFuncSetAttribute(MyHMM_14353780703777_kernel,
                         cudaFuncAttributeMaxDynamicSharedMemorySize, (int)smem);
    MyHMM_14353780703777_kernel<<<HB, 128, smem>>>(x, means, stds, logA, logpi, out, T);
}

// round 9
// speedup vs baseline: 1.5408x; 1.5408x over previous
#include <cuda_runtime.h>
#include <cuda_bf16.h>
#include <cstdint>

#define HB 128      // batch
#define HC 64       // states
#define NEG_INF (-3.402823466e38f)
// float32(0.5 * log(2*pi))
#define HALF_LOG2PI 0.91893853320467274178f

__device__ __forceinline__ float warp_max_bfly(float v) {
    #pragma unroll
    for (int off = 16; off >= 1; off >>= 1)
        v = fmaxf(v, __shfl_xor_sync(0xffffffff, v, off));
    return v;
}

// ---------- ref-exact emission (Viterbi path; matches XLA f32 op sequence) ----------
__device__ __forceinline__ float emis_ref(float4 xv, const float* mu,
                                          const float* sg, const float* lsg) {
    float z0 = __fdiv_rn(__fsub_rn(xv.x, mu[0]), sg[0]);
    float z1 = __fdiv_rn(__fsub_rn(xv.y, mu[1]), sg[1]);
    float z2 = __fdiv_rn(__fsub_rn(xv.z, mu[2]), sg[2]);
    float z3 = __fdiv_rn(__fsub_rn(xv.w, mu[3]), sg[3]);
    float e0 = __fsub_rn(__fsub_rn(__fmul_rn(__fmul_rn(-0.5f, z0), z0), lsg[0]), HALF_LOG2PI);
    float e1 = __fsub_rn(__fsub_rn(__fmul_rn(__fmul_rn(-0.5f, z1), z1), lsg[1]), HALF_LOG2PI);
    float e2 = __fsub_rn(__fsub_rn(__fmul_rn(__fmul_rn(-0.5f, z2), z2), lsg[2]), HALF_LOG2PI);
    float e3 = __fsub_rn(__fsub_rn(__fmul_rn(__fmul_rn(-0.5f, z3), z3), lsg[3]), HALF_LOG2PI);
    return __fadd_rn(__fadd_rn(__fadd_rn(e0, e1), e2), e3);
}

// ---------- fast emission (forward path; tolerance is loose there) ----------
// lp = K - 0.5 * sum z^2,  z_d = x_d*iv_d - muiv_d  (1 FFMA each)
__device__ __forceinline__ float emis_fast(float4 xv, const float* iv,
                                           const float* muiv, float K) {
    float z0 = fmaf(xv.x, iv[0], muiv[0]);
    float z1 = fmaf(xv.y, iv[1], muiv[1]);
    float z2 = fmaf(xv.z, iv[2], muiv[2]);
    float z3 = fmaf(xv.w, iv[3], muiv[3]);
    float qa = fmaf(z0, z0, z1 * z1);
    float qb = fmaf(z2, z2, z3 * z3);
    return fmaf(-0.5f, qa + qb, K);
}

__global__ __launch_bounds__(128, 1)
void MyHMM_14353780703777_kernel(const float* __restrict__ x,
                                 const float* __restrict__ means,
                                 const float* __restrict__ stds,
                                 const float* __restrict__ logA,
                                 const float* __restrict__ logpi,
                                 float* __restrict__ out, int T) {
    extern __shared__ char smem[];
    float4* xs          = (float4*)smem;                       // T * 16 bytes
    float*  abuf        = (float*)(smem + 16 * (size_t)T);     // 2*64 (forward alpha dbl-buf)
    float*  dbuf        = abuf + 128;                          // 2*64 (viterbi d dbl-buf)
    float*  Abuf        = dbuf + 128;                          // 64*65 padded raw logA
    float*  rowmx       = Abuf + 64 * 65;                      // 64 row maxes
    float*  rowls       = rowmx + 64;                          // 64 row lse's
    float*  piaux       = rowls + 64;                          // [0]=pimax, [1]=pilse (pad 16)
    unsigned char* psi  = (unsigned char*)(piaux + 16);        // (T-1)*64 backpointers

    const int b = blockIdx.x;
    const int tid = threadIdx.x;
    const float* xb = x + (size_t)b * T * 6;

    // ---- preload x[b, :, 0:4] as float4 ----
    for (int i = tid; i < T; i += 128) {
        const float* p = xb + i * 6;
        xs[i] = make_float4(p[0], p[1], p[2], p[3]);
    }
    // ---- load raw log_A into padded smem ----
    for (int i = tid; i < HC * HC; i += 128) {
        Abuf[(i >> 6) * 65 + (i & 63)] = logA[i];
    }
    __syncthreads();

    // ---- log_softmax prep (accurate expf/logf, sequential sums -> ref-exact) ----
    if (tid < HC) {
        const int r = tid;
        float mx = NEG_INF;
        #pragma unroll 8
        for (int j = 0; j < HC; j++) mx = fmaxf(mx, Abuf[r * 65 + j]);
        float s = 0.0f;
        #pragma unroll 8
        for (int j = 0; j < HC; j++)
            s = __fadd_rn(s, expf(__fsub_rn(Abuf[r * 65 + j], mx)));
        rowmx[r] = mx;
        rowls[r] = logf(s);
    }
    if (tid == 0) {
        float mx = NEG_INF;
        for (int j = 0; j < HC; j++) mx = fmaxf(mx, logpi[j]);
        float s = 0.0f;
        for (int j = 0; j < HC; j++)
            s = __fadd_rn(s, expf(__fsub_rn(logpi[j], mx)));
        piaux[0] = mx;
        piaux[1] = logf(s);
    }
    __syncthreads();
    const float pimx = piaux[0];
    const float pils = piaux[1];

    if (tid < 32) {
        // ========== FORWARD (1 warp, 2 states/thread, prob-space, deferred renorm) ==========
        const int c0 = tid, c1 = tid + 32;
        float iv0[4], muiv0[4], iv1[4], muiv1[4];
        float K0 = 0.0f, K1 = 0.0f;
        #pragma unroll
        for (int d = 0; d < 4; d++) {
            float s0 = fmaxf(stds[c0 * 6 + d], 0.0f) + 0.1f;
            float s1 = fmaxf(stds[c1 * 6 + d], 0.0f) + 0.1f;
            iv0[d] = 1.0f / s0;                     iv1[d] = 1.0f / s1;
            muiv0[d] = -means[c0 * 6 + d] * iv0[d]; muiv1[d] = -means[c1 * 6 + d] * iv1[d];
            K0 += -logf(s0) - HALF_LOG2PI;
            K1 += -logf(s1) - HALF_LOG2PI;
        }
        const float pil0 = (logpi[c0] - pimx) - pils;
        const float pil1 = (logpi[c1] - pimx) - pils;

        // register-resident transition columns (prob space)
        float Ae0[64], Ae1[64];
        #pragma unroll
        for (int j = 0; j < 64; j++) {
            Ae0[j] = __expf((Abuf[j * 65 + c0] - rowmx[j]) - rowls[j]);
            Ae1[j] = __expf((Abuf[j * 65 + c1] - rowmx[j]) - rowls[j]);
        }

        // t = 0
        float4 xv = xs[0];
        float lpA = emis_fast(xv, iv0, muiv0, K0) + pil0;
        float lpB = emis_fast(xv, iv1, muiv1, K1) + pil1;
        float g = warp_max_bfly(fmaxf(lpA, lpB));
        float u0 = __expf(lpA - g);
        float u1 = __expf(lpB - g);
        double acc = (double)g;

        float* aprev = abuf;
        float* acur  = abuf + 64;
        aprev[c0] = u0; aprev[c1] = u1;
        __syncwarp();

        float rprev = 1.0f;           // 1/m_{t-1}
        float lpend = 0.0f;           // log(m_{t-1}) pending
        float w0 = u0, w1 = u1;

        for (int t = 1; t < T; t++) {
            float4 xq = xs[t];
            float l0 = emis_fast(xq, iv0, muiv0, K0);
            float l1 = emis_fast(xq, iv1, muiv1, K1);
            // reduction (MIO) overlaps the matvec (FMA)
            float gt = warp_max_bfly(fmaxf(l0, l1));

            float v0a = 0.0f, v0b = 0.0f, v1a = 0.0f, v1b = 0.0f;
            #pragma unroll
            for (int j = 0; j < 64; j += 4) {
                float4 a = *(const float4*)(aprev + j);
                v0a = fmaf(a.x, Ae0[j],     v0a);
                v1a = fmaf(a.x, Ae1[j],     v1a);
                v0b = fmaf(a.y, Ae0[j + 1], v0b);
                v1b = fmaf(a.y, Ae1[j + 1], v1b);
                v0a = fmaf(a.z, Ae0[j + 2], v0a);
                v1a = fmaf(a.z, Ae1[j + 2], v1a);
                v0b = fmaf(a.w, Ae0[j + 3], v0b);
                v1b = fmaf(a.w, Ae1[j + 3], v1b);
            }
            float e0 = __expf(l0 - gt) * rprev;
            float e1 = __expf(l1 - gt) * rprev;
            w0 = e0 * (v0a + v0b);
            w1 = e1 * (v1a + v1b);
            acur[c0] = w0; acur[c1] = w1;       // store BEFORE reduction
            __syncwarp();
            acc += (double)gt + (double)lpend;

            float m = warp_max_bfly(fmaxf(w0, w1));
            rprev = __frcp_rn(m);
            lpend = __logf(m);

            float* tmp = aprev; aprev = acur; acur = tmp;
        }

        // logp_x = acc + log(m_{T-1}) + log(sum of last stored w)
        float s = w0 + w1;
        #pragma unroll
        for (int off = 16; off >= 1; off >>= 1)
            s += __shfl_xor_sync(0xffffffff, s, off);
        if (tid == 0) out[b] = (float)(acc + (double)lpend + (double)__logf(s));

    } else if (tid >= 64) {
        // ========== VITERBI (2 warps, 1 state/thread, ref-exact f32 ops) ==========
        const int c = tid - 64;
        float mu[4], sg[4], lsg[4];
        #pragma unroll
        for (int d = 0; d < 4; d++) {
            sg[d]  = __fadd_rn(fmaxf(stds[c * 6 + d], 0.0f), 0.1f);
            mu[d]  = means[c * 6 + d];
            lsg[d] = logf(sg[d]);
        }
        const float pil = __fsub_rn(__fsub_rn(logpi[c], pimx), pils);

        float Al[64];
        #pragma unroll
        for (int j = 0; j < 64; j++)
            Al[j] = __fsub_rn(__fsub_rn(Abuf[j * 65 + c], rowmx[j]), rowls[j]);

        float* dprev = dbuf;
        float* dcur  = dbuf + 64;

        float4 xv = xs[0];
        dprev[c] = __fadd_rn(emis_ref(xv, mu, sg, lsg), pil);
        asm volatile("bar.sync 1, 64;" ::: "memory");

        for (int t = 1; t < T; t++) {
            float4 xq = xs[t];
            float lp = emis_ref(xq, mu, sg, lsg);

            // 8 independent (best, argmax) chains over contiguous j-octets,
            // then a strict-'>' combine tree (left keeps ties) ==
            // first-max ascending scan == jnp.argmax semantics, bit-identical.
            float cb[8];
            int   ci[8];
            #pragma unroll
            for (int g = 0; g < 8; g++) {
                const int base = g * 8;
                float4 a0 = *(const float4*)(dprev + base);
                float4 a1 = *(const float4*)(dprev + base + 4);
                float bst = __fadd_rn(a0.x, Al[base]);
                int   idx = base;
                float v;
                v = __fadd_rn(a0.y, Al[base + 1]); if (v > bst) { bst = v; idx = base + 1; }
                v = __fadd_rn(a0.z, Al[base + 2]); if (v > bst) { bst = v; idx = base + 2; }
                v = __fadd_rn(a0.w, Al[base + 3]); if (v > bst) { bst = v; idx = base + 3; }
                v = __fadd_rn(a1.x, Al[base + 4]); if (v > bst) { bst = v; idx = base + 4; }
                v = __fadd_rn(a1.y, Al[base + 5]); if (v > bst) { bst = v; idx = base + 5; }
                v = __fadd_rn(a1.z, Al[base + 6]); if (v > bst) { bst = v; idx = base + 6; }
                v = __fadd_rn(a1.w, Al[base + 7]); if (v > bst) { bst = v; idx = base + 7; }
                cb[g] = bst; ci[g] = idx;
            }
            // combine tree: right wins only if strictly greater (lower index keeps ties)
            #pragma unroll
            for (int stp = 1; stp < 8; stp <<= 1)
                #pragma unroll
                for (int g = 0; g < 8; g += 2 * stp)
                    if (cb[g + stp] > cb[g]) { cb[g] = cb[g + stp]; ci[g] = ci[g + stp]; }

            dcur[c] = __fadd_rn(cb[0], lp);
            psi[(t - 1) * 64 + c] = (unsigned char)ci[0];
            asm volatile("bar.sync 1, 64;" ::: "memory");
            float* tmp = dprev; dprev = dcur; dcur = tmp;
        }

        // backtrack (single thread; psi in smem -> LDS-latency chase)
        if (c == 0) {
            float bb = dprev[0]; int cl = 0;
            #pragma unroll 8
            for (int j = 1; j < 64; j++) {
                float v = dprev[j];
                if (v > bb) { bb = v; cl = j; }
            }
            float* oc = out + HB + (size_t)b * T;
            int cc = cl;
            oc[T - 1] = (float)cc;
            for (int t = T - 2; t >= 0; --t) {
                cc = psi[t * 64 + cc];
                oc[t] = (float)cc;
            }
        }
    }
    // tid 32..63: idle warp (never touches named barrier 1)
}

extern "C" void kernel_launch(void* const* d_in, const int* in_sizes, int n_in,
                              void* d_out, int out_size) {
    const float* x      = (const float*)d_in[0];
    const float* means  = (const float*)d_in[1];
    const float* stds   = (const float*)d_in[2];
    const float* logA   = (const float*)d_in[3];
    const float* logpi  = (const float*)d_in[4];
    float* out = (float*)d_out;

    int T = in_sizes[0] / (HB * 6);   // 2050

    size_t smem = 16 * (size_t)T          // xs
                + 128 * sizeof(float)     // abuf
                + 128 * sizeof(float)     // dbuf
                + 64 * 65 * sizeof(float) // Abuf (padded)
                + (64 + 64 + 16) * sizeof(float) // rowmx, rowls, piaux
                + (size_t)(T - 1) * 64;   // psi

    cudaFuncSetAttribute(MyHMM_14353780703777_kernel,
                         cudaFuncAttributeMaxDynamicSharedMemorySize, (int)smem);
    MyHMM_14353780703777_kernel<<<HB, 128, smem>>>(x, means, stds, logA, logpi, out, T);
}